// round 14
// baseline (speedup 1.0000x reference)
#include <cuda_runtime.h>
#include <cuda_fp16.h>
#include <math.h>
#include <stdint.h>
#include <stdlib.h>

// ---------------------------------------------------------------------------
// GAT 4-layer forward.  N=100000, E=1600000, 128 feats (4h x 32d).
// R14: R13's two-warp-per-node agg with the pair-combine FIXED: the softmax
// normalizer s is per-HEAD (head = lane>>3), so partials must be published
// per lane (sS[4][32]), not as a single scalar.  gemv4 stays fused into
// agg3.  TC GEMM (R12), CSR overlap, agg4 unchanged.
// ---------------------------------------------------------------------------

#define MAXN 100000
#define MAXE 1600000

__device__ uint4 g_hh[MAXN * 16];     // projected features, fp16 (256B/row)
__device__ float g_act[MAXN * 128];   // activations (updated in place)
__device__ float g_el[MAXN * 4];
__device__ float g_er[MAXN * 4];
__device__ int   g_deg[MAXN];
__device__ int   g_cur[MAXN];
__device__ int   g_off[MAXN + 1];
__device__ int   g_csrc[MAXE];
__device__ int   g_bsum[128];
__device__ int   g_boff[128];
__device__ float g_h4[MAXN * 2];
__device__ float g_res4[MAXN * 2];
__device__ float g_el4[MAXN];
__device__ float g_er4[MAXN];

// ---------------------------------------------------------------------------
// CSR build
// ---------------------------------------------------------------------------
__global__ void zero_kernel(int n) {
    int i = blockIdx.x * blockDim.x + threadIdx.x;
    if (i < n) { g_deg[i] = 0; g_cur[i] = 0; }
}

__global__ void hist_kernel(const int* __restrict__ dst, int e) {
    int i = blockIdx.x * blockDim.x + threadIdx.x;
    if (i < e) atomicAdd(&g_deg[dst[i]], 1);
}

__global__ void scan1_kernel(int n) {
    __shared__ int sm[1024];
    int t = threadIdx.x;
    int i = blockIdx.x * 1024 + t;
    int v = (i < n) ? g_deg[i] : 0;
    sm[t] = v;
    __syncthreads();
    for (int o = 1; o < 1024; o <<= 1) {
        int u = (t >= o) ? sm[t - o] : 0;
        __syncthreads();
        sm[t] += u;
        __syncthreads();
    }
    if (i < n) g_off[i] = sm[t] - v;
    if (t == 1023) g_bsum[blockIdx.x] = sm[1023];
}

__global__ void scan2_kernel(int nb, int n) {
    __shared__ int sm[128];
    int t = threadIdx.x;
    int v = (t < nb) ? g_bsum[t] : 0;
    sm[t] = v;
    __syncthreads();
    for (int o = 1; o < 128; o <<= 1) {
        int u = (t >= o) ? sm[t - o] : 0;
        __syncthreads();
        sm[t] += u;
        __syncthreads();
    }
    if (t < nb) g_boff[t] = sm[t] - v;
    if (t == 127) g_off[n] = sm[127];
}

__global__ void scan3_kernel(int n) {
    int i = blockIdx.x * blockDim.x + threadIdx.x;
    if (i < n) g_off[i] += g_boff[i >> 10];
}

__global__ void scatter_kernel(const int* __restrict__ src,
                               const int* __restrict__ dst, int e) {
    int i = blockIdx.x * blockDim.x + threadIdx.x;
    if (i < e) {
        int d = dst[i];
        int pos = atomicAdd(&g_cur[d], 1);
        g_csrc[g_off[d] + pos] = src[i];
    }
}

// ---------------------------------------------------------------------------
// Touch kernel (prewarm only)
// ---------------------------------------------------------------------------
__global__ void touch_kernel() {
    long i = (long)blockIdx.x * blockDim.x + threadIdx.x;
    long tot = (long)MAXN * 128;
    if (i < (long)MAXN * 16) g_hh[i] = make_uint4(0, 0, 0, 0);
    if (i < tot) g_act[i] = 0.f;
    if (i < MAXE) g_csrc[i] = 0;
    if (i < MAXN) {
        g_el[i * 4] = 0.f; g_er[i * 4] = 0.f;
        g_el4[i] = 0.f; g_er4[i] = 0.f;
        g_h4[i * 2] = 0.f; g_res4[i * 2] = 0.f;
        g_deg[i] = 0; g_cur[i] = 0; g_off[i] = 0;
    }
    if (i < 128) { g_bsum[i] = 0; g_boff[i] = 0; }
}

// ---------------------------------------------------------------------------
// Tensor-core GEMM: g_hh[n,128](fp16) = X[n,128] @ W[128,128] + el/er.
// ---------------------------------------------------------------------------
#define ASTRIDE 136
#define SMEM_TC (2 * 128 * ASTRIDE * 2)

__global__ __launch_bounds__(256) void gemm_tc_kernel(
    const float* __restrict__ X_ext, const float* __restrict__ W,
    const float* __restrict__ al, const float* __restrict__ ar,
    int n, int use_act) {
    const float* X = use_act ? (const float*)g_act : X_ext;
    extern __shared__ __half sm[];
    __half* As = sm;
    __half* Bs = sm + 128 * ASTRIDE;

    int tid = threadIdx.x;
    int lane = tid & 31;
    int wid = tid >> 5;
    int row0 = blockIdx.x * 128;

    for (int i = tid; i < 128 * 32; i += 256) {
        int r = i >> 5;
        int kq = i & 31;
        int row = row0 + r;
        float4 v = make_float4(0.f, 0.f, 0.f, 0.f);
        if (row < n) v = ((const float4*)X)[row * 32 + kq];
        __half2 p0 = __floats2half2_rn(v.x, v.y);
        __half2 p1 = __floats2half2_rn(v.z, v.w);
        uint2 pk;
        pk.x = *reinterpret_cast<unsigned*>(&p0);
        pk.y = *reinterpret_cast<unsigned*>(&p1);
        *reinterpret_cast<uint2*>(&As[r * ASTRIDE + kq * 4]) = pk;
    }
    for (int i = tid; i < 128 * 32; i += 256) {
        int r = i >> 5;
        int kq = i & 31;
        float4 v = ((const float4*)W)[r * 32 + kq];
        __half2 p0 = __floats2half2_rn(v.x, v.y);
        __half2 p1 = __floats2half2_rn(v.z, v.w);
        uint2 pk;
        pk.x = *reinterpret_cast<unsigned*>(&p0);
        pk.y = *reinterpret_cast<unsigned*>(&p1);
        *reinterpret_cast<uint2*>(&Bs[r * ASTRIDE + kq * 4]) = pk;
    }
    __syncthreads();

    int mrow = wid * 16;
    int row_sel = lane & 15;
    int col_off8 = (lane >> 4) << 3;
    float c[16][4];
#pragma unroll
    for (int a = 0; a < 16; a++)
#pragma unroll
        for (int j = 0; j < 4; j++) c[a][j] = 0.f;

#pragma unroll
    for (int ks = 0; ks < 8; ks++) {
        unsigned a0, a1, a2, a3;
        {
            unsigned addr = (unsigned)__cvta_generic_to_shared(
                &As[(mrow + row_sel) * ASTRIDE + ks * 16 + col_off8]);
            asm volatile(
                "ldmatrix.sync.aligned.m8n8.x4.shared.b16 {%0,%1,%2,%3}, [%4];"
                : "=r"(a0), "=r"(a1), "=r"(a2), "=r"(a3) : "r"(addr));
        }
#pragma unroll
        for (int nb2 = 0; nb2 < 8; nb2++) {
            unsigned b0, b1, b2, b3;
            unsigned addr = (unsigned)__cvta_generic_to_shared(
                &Bs[(ks * 16 + row_sel) * ASTRIDE + nb2 * 16 + col_off8]);
            asm volatile(
                "ldmatrix.sync.aligned.m8n8.x4.trans.shared.b16 {%0,%1,%2,%3}, [%4];"
                : "=r"(b0), "=r"(b1), "=r"(b2), "=r"(b3) : "r"(addr));
            int na = nb2 * 2;
            asm volatile(
                "mma.sync.aligned.m16n8k16.row.col.f32.f16.f16.f32 "
                "{%0,%1,%2,%3}, {%4,%5,%6,%7}, {%8,%9}, {%0,%1,%2,%3};"
                : "+f"(c[na][0]), "+f"(c[na][1]), "+f"(c[na][2]), "+f"(c[na][3])
                : "r"(a0), "r"(a1), "r"(a2), "r"(a3), "r"(b0), "r"(b1));
            asm volatile(
                "mma.sync.aligned.m16n8k16.row.col.f32.f16.f16.f32 "
                "{%0,%1,%2,%3}, {%4,%5,%6,%7}, {%8,%9}, {%0,%1,%2,%3};"
                : "+f"(c[na + 1][0]), "+f"(c[na + 1][1]), "+f"(c[na + 1][2]), "+f"(c[na + 1][3])
                : "r"(a0), "r"(a1), "r"(a2), "r"(a3), "r"(b2), "r"(b3));
        }
    }
    __syncthreads();

    {
        int r0 = mrow + (lane >> 2);
        int cc = (lane & 3) * 2;
#pragma unroll
        for (int na = 0; na < 16; na++) {
            __half2 lo = __floats2half2_rn(c[na][0], c[na][1]);
            __half2 hi = __floats2half2_rn(c[na][2], c[na][3]);
            *reinterpret_cast<unsigned*>(&As[r0 * ASTRIDE + na * 8 + cc]) =
                *reinterpret_cast<unsigned*>(&lo);
            *reinterpret_cast<unsigned*>(&As[(r0 + 8) * ASTRIDE + na * 8 + cc]) =
                *reinterpret_cast<unsigned*>(&hi);
        }
    }
    __syncthreads();

    {
        int r = tid >> 1;
        int hsel = tid & 1;
        int row = row0 + r;
        if (row < n) {
            uint4 cv[8];
#pragma unroll
            for (int j = 0; j < 8; j++)
                cv[j] = *reinterpret_cast<uint4*>(&As[r * ASTRIDE + hsel * 64 + j * 8]);
#pragma unroll
            for (int j = 0; j < 8; j++)
                g_hh[row * 16 + hsel * 8 + j] = cv[j];
            int h0 = hsel * 2;
            float el0 = 0.f, er0 = 0.f, el1 = 0.f, er1 = 0.f;
#pragma unroll
            for (int j = 0; j < 8; j++) {
                const __half2* hp = reinterpret_cast<const __half2*>(&cv[j]);
#pragma unroll
                for (int q = 0; q < 4; q++) {
                    float2 f = __half22float2(hp[q]);
                    int d = (j * 8 + q * 2) & 31;
                    if (j < 4) {
                        el0 += f.x * al[h0 * 32 + d]     + f.y * al[h0 * 32 + d + 1];
                        er0 += f.x * ar[h0 * 32 + d]     + f.y * ar[h0 * 32 + d + 1];
                    } else {
                        el1 += f.x * al[(h0 + 1) * 32 + d] + f.y * al[(h0 + 1) * 32 + d + 1];
                        er1 += f.x * ar[(h0 + 1) * 32 + d] + f.y * ar[(h0 + 1) * 32 + d + 1];
                    }
                }
            }
            *reinterpret_cast<float2*>(&g_el[row * 4 + h0]) = make_float2(el0, el1);
            *reinterpret_cast<float2*>(&g_er[row * 4 + h0]) = make_float2(er0, er1);
        }
    }
}

// ---------------------------------------------------------------------------
// Agg: 2 warps per dst node, smem pair-combine with PER-LANE normalizer
// publish (s is head-specific: head = lane>>3).  Single pass, fused
// residual+bias+ELU; fuse4 adds the layer-4 projections.
// ---------------------------------------------------------------------------
__device__ __forceinline__ float lrelu(float x) { return x > 0.f ? x : 0.2f * x; }

__global__ __launch_bounds__(256) void agg_kernel(
    const float* prev_ext, const float* __restrict__ bias, int n, int use_act,
    int fuse4, const float* __restrict__ W4, const float* __restrict__ Wres4,
    const float* __restrict__ al4, const float* __restrict__ ar4) {
    __shared__ float sAcc[4][32][4];
    __shared__ float sS[4][32];

    int wib = threadIdx.x >> 5;          // warp in block (0..7)
    int pair = wib >> 1;                 // node slot (0..3)
    int sub = wib & 1;                   // half-selector
    int w = blockIdx.x * 4 + pair;       // node
    int lane = threadIdx.x & 31;
    int head = lane >> 3;
    bool valid = w < n;

    const float* prev = use_act ? (const float*)g_act : prev_ext;

    int e0 = 0, e1 = 0;
    if (valid) { e0 = g_off[w]; e1 = g_off[w + 1]; }
    int mid = e0 + ((e1 - e0 + 1) >> 1);
    int a = sub ? mid : e0;
    int b = sub ? e1 : mid;

    float erh = valid ? __ldg(&g_er[w * 4 + head]) : 0.f;

    const uint2* hp = (const uint2*)g_hh;
    float s = 0.f;
    float4 acc = make_float4(0.f, 0.f, 0.f, 0.f);
#pragma unroll 4
    for (int i = a; i < b; ++i) {
        int sn = __ldg(&g_csrc[i]);
        float e = lrelu(__ldg(&g_el[sn * 4 + head]) + erh);
        float p = __expf(e);
        s += p;
        uint2 raw = __ldg(&hp[sn * 32 + lane]);
        __half2 ha = *reinterpret_cast<const __half2*>(&raw.x);
        __half2 hb = *reinterpret_cast<const __half2*>(&raw.y);
        float2 f01 = __half22float2(ha);
        float2 f23 = __half22float2(hb);
        acc.x += p * f01.x;
        acc.y += p * f01.y;
        acc.z += p * f23.x;
        acc.w += p * f23.y;
    }

    // pair combine: odd warp publishes per-lane partials, even warp merges.
    if (sub == 1) {
        sAcc[pair][lane][0] = acc.x;
        sAcc[pair][lane][1] = acc.y;
        sAcc[pair][lane][2] = acc.z;
        sAcc[pair][lane][3] = acc.w;
        sS[pair][lane] = s;              // per-lane: preserves per-head s
    }
    __syncthreads();
    if (sub == 1 || !valid) return;

    acc.x += sAcc[pair][lane][0];
    acc.y += sAcc[pair][lane][1];
    acc.z += sAcc[pair][lane][2];
    acc.w += sAcc[pair][lane][3];
    s += sS[pair][lane];
    float inv = s > 0.f ? 1.f / s : 0.f;

    float4 r = ((const float4*)prev)[w * 32 + lane];
    float4 bb = ((const float4*)bias)[lane];
    float o0 = acc.x * inv + r.x + bb.x;
    float o1 = acc.y * inv + r.y + bb.y;
    float o2 = acc.z * inv + r.z + bb.z;
    float o3 = acc.w * inv + r.w + bb.w;
    o0 = o0 > 0.f ? o0 : expm1f(o0);
    o1 = o1 > 0.f ? o1 : expm1f(o1);
    o2 = o2 > 0.f ? o2 : expm1f(o2);
    o3 = o3 > 0.f ? o3 : expm1f(o3);
    ((float4*)g_act)[w * 32 + lane] = make_float4(o0, o1, o2, o3);

    if (fuse4) {
        float4 w0 = ((const float4*)W4)[lane * 2];
        float4 w1 = ((const float4*)W4)[lane * 2 + 1];
        float4 q0v = ((const float4*)Wres4)[lane * 2];
        float4 q1v = ((const float4*)Wres4)[lane * 2 + 1];
        float h40 = o0 * w0.x + o1 * w0.z + o2 * w1.x + o3 * w1.z;
        float h41 = o0 * w0.y + o1 * w0.w + o2 * w1.y + o3 * w1.w;
        float q40 = o0 * q0v.x + o1 * q0v.z + o2 * q1v.x + o3 * q1v.z;
        float q41 = o0 * q0v.y + o1 * q0v.w + o2 * q1v.y + o3 * q1v.w;
#pragma unroll
        for (int o = 16; o; o >>= 1) {
            h40 += __shfl_xor_sync(0xffffffffu, h40, o);
            h41 += __shfl_xor_sync(0xffffffffu, h41, o);
            q40 += __shfl_xor_sync(0xffffffffu, q40, o);
            q41 += __shfl_xor_sync(0xffffffffu, q41, o);
        }
        if (lane == 0) {
            g_h4[w * 2] = h40;
            g_h4[w * 2 + 1] = h41;
            g_res4[w * 2] = q40;
            g_res4[w * 2 + 1] = q41;
            g_el4[w] = h40 * al4[0] + h41 * al4[1];
            g_er4[w] = h40 * ar4[0] + h41 * ar4[1];
        }
    }
}

// Single-pass layer-4 aggregation: lanes stride edges, one warp reduction.
__global__ __launch_bounds__(256) void agg4_kernel(
    const float* __restrict__ b4, float* __restrict__ out, int n) {
    int w = (blockIdx.x * blockDim.x + threadIdx.x) >> 5;
    if (w >= n) return;
    int lane = threadIdx.x & 31;
    int e0 = g_off[w];
    int e1 = g_off[w + 1];
    float erv = g_er4[w];

    float s = 0.f, a0 = 0.f, a1 = 0.f;
    for (int i = e0 + lane; i < e1; i += 32) {
        int sn = g_csrc[i];
        float e = lrelu(g_el4[sn] + erv);
        float p = __expf(e);
        s += p;
        float2 hv = ((const float2*)g_h4)[sn];
        a0 += p * hv.x;
        a1 += p * hv.y;
    }
#pragma unroll
    for (int o = 16; o; o >>= 1) {
        s  += __shfl_xor_sync(0xffffffffu, s, o);
        a0 += __shfl_xor_sync(0xffffffffu, a0, o);
        a1 += __shfl_xor_sync(0xffffffffu, a1, o);
    }
    float inv = s > 0.f ? 1.f / s : 0.f;
    if (lane == 0) {
        out[w * 2]     = a0 * inv + g_res4[w * 2]     + b4[0];
        out[w * 2 + 1] = a1 * inv + g_res4[w * 2 + 1] + b4[1];
    }
}

// ---------------------------------------------------------------------------
// Constructor: EAGER loading, context, smem attribute, prewarm, aux stream.
// ---------------------------------------------------------------------------
namespace {
cudaStream_t g_saux;
cudaEvent_t  g_ev_fork;
cudaEvent_t  g_ev_join;

struct Prewarm {
    Prewarm() {
        setenv("CUDA_MODULE_LOADING", "EAGER", 1);
        cudaFree(0);

        cudaStreamCreateWithFlags(&g_saux, cudaStreamNonBlocking);
        cudaEventCreateWithFlags(&g_ev_fork, cudaEventDisableTiming);
        cudaEventCreateWithFlags(&g_ev_join, cudaEventDisableTiming);
        cudaFuncSetAttribute(gemm_tc_kernel,
                             cudaFuncAttributeMaxDynamicSharedMemorySize, SMEM_TC);

        void* ph = nullptr;
        void* pd = nullptr;
        cudaGetSymbolAddress(&ph, g_act);
        cudaGetSymbolAddress(&pd, g_deg);
        const float* fp = (const float*)ph;
        const int*   ip = (const int*)pd;
        float*       op = (float*)ph;

        int nbn = (MAXN + 255) / 256;
        int nbe = (MAXE + 255) / 256;
        int nbw = (MAXN + 7) / 8;
        int nba = (MAXN + 3) / 4;
        int nbg = (MAXN + 127) / 128;
        int nbs = (MAXN + 1023) / 1024;
        long tot = (long)MAXN * 128;
        int nbt = (int)((tot + 255) / 256);

        touch_kernel<<<nbt, 256>>>();
        zero_kernel<<<nbn, 256>>>(0);
        hist_kernel<<<nbe, 256>>>(ip, 0);
        scan1_kernel<<<nbs, 1024>>>(0);
        scan2_kernel<<<1, 128>>>(0, 0);
        scan3_kernel<<<nbn, 256>>>(0);
        scatter_kernel<<<nbe, 256>>>(ip, ip, 0);
        gemm_tc_kernel<<<nbg, 256, SMEM_TC>>>(fp, fp, fp, fp, 0, 1);
        agg_kernel<<<nba, 256>>>(fp, fp, 0, 1, 1, fp, fp, fp, fp);
        agg4_kernel<<<nbw, 256>>>(fp, op, 0);
        zero_kernel<<<nbn, 256, 0, g_saux>>>(0);
        touch_kernel<<<nbt, 256>>>();
        cudaDeviceSynchronize();
    }
};
Prewarm g_prewarm;
}  // namespace

// ---------------------------------------------------------------------------
// Launch
// ---------------------------------------------------------------------------
extern "C" void kernel_launch(void* const* d_in, const int* in_sizes, int n_in,
                              void* d_out, int out_size) {
    const float* x     = (const float*)d_in[0];
    const int*   src   = (const int*)d_in[1];
    const int*   dst   = (const int*)d_in[2];
    const float* W1    = (const float*)d_in[3];
    const float* al1   = (const float*)d_in[4];
    const float* ar1   = (const float*)d_in[5];
    const float* b1    = (const float*)d_in[6];
    const float* W2    = (const float*)d_in[7];
    const float* al2   = (const float*)d_in[8];
    const float* ar2   = (const float*)d_in[9];
    const float* b2    = (const float*)d_in[10];
    const float* W3    = (const float*)d_in[11];
    const float* al3   = (const float*)d_in[12];
    const float* ar3   = (const float*)d_in[13];
    const float* b3    = (const float*)d_in[14];
    const float* W4    = (const float*)d_in[15];
    const float* al4   = (const float*)d_in[16];
    const float* ar4   = (const float*)d_in[17];
    const float* b4    = (const float*)d_in[18];
    const float* Wres4 = (const float*)d_in[19];
    float* out = (float*)d_out;

    int n = in_sizes[0] / 128;
    int e = in_sizes[1];
    int nb = (n + 1023) / 1024;

    int nbw = (n + 7) / 8;
    int nba = (n + 3) / 4;
    int nbg = (n + 127) / 128;

    // Fork: CSR build on aux stream, layer-1 GEMM on main stream.
    cudaEventRecord(g_ev_fork, 0);
    cudaStreamWaitEvent(g_saux, g_ev_fork, 0);

    zero_kernel<<<(n + 255) / 256, 256, 0, g_saux>>>(n);
    hist_kernel<<<(e + 255) / 256, 256, 0, g_saux>>>(dst, e);
    scan1_kernel<<<nb, 1024, 0, g_saux>>>(n);
    scan2_kernel<<<1, 128, 0, g_saux>>>(nb, n);
    scan3_kernel<<<(n + 255) / 256, 256, 0, g_saux>>>(n);
    scatter_kernel<<<(e + 255) / 256, 256, 0, g_saux>>>(src, dst, e);
    cudaEventRecord(g_ev_join, g_saux);

    gemm_tc_kernel<<<nbg, 256, SMEM_TC>>>(x, W1, al1, ar1, n, 0);

    cudaStreamWaitEvent(0, g_ev_join, 0);
    agg_kernel<<<nba, 256>>>(x, b1, n, 0, 0, nullptr, nullptr, nullptr, nullptr);

    gemm_tc_kernel<<<nbg, 256, SMEM_TC>>>(nullptr, W2, al2, ar2, n, 1);
    agg_kernel<<<nba, 256>>>(nullptr, b2, n, 1, 0, nullptr, nullptr, nullptr, nullptr);

    gemm_tc_kernel<<<nbg, 256, SMEM_TC>>>(nullptr, W3, al3, ar3, n, 1);
    agg_kernel<<<nba, 256>>>(nullptr, b3, n, 1, 1, W4, Wres4, al4, ar4);

    agg4_kernel<<<nbw, 256>>>(b4, out, n);
}

// round 15
// speedup vs baseline: 1.0891x; 1.0891x over previous
#include <cuda_runtime.h>
#include <cuda_fp16.h>
#include <math.h>
#include <stdint.h>
#include <stdlib.h>

// ---------------------------------------------------------------------------
// GAT 4-layer forward.  N=100000, E=1600000, 128 feats (4h x 32d).
// R15: revert agg to the R12 single-warp-per-node form (both multi-warp/
// multi-edge restructurings regressed), keep ONLY the R13 gemv4 fusion:
// agg3's epilogue computes the layer-4 projections from the activation row
// it just produced (one less kernel + 51MB read).  TC GEMM (R12), CSR
// overlap, agg4 unchanged.
// ---------------------------------------------------------------------------

#define MAXN 100000
#define MAXE 1600000

__device__ uint4 g_hh[MAXN * 16];     // projected features, fp16 (256B/row)
__device__ float g_act[MAXN * 128];   // activations (updated in place)
__device__ float g_el[MAXN * 4];
__device__ float g_er[MAXN * 4];
__device__ int   g_deg[MAXN];
__device__ int   g_cur[MAXN];
__device__ int   g_off[MAXN + 1];
__device__ int   g_csrc[MAXE];
__device__ int   g_bsum[128];
__device__ int   g_boff[128];
__device__ float g_h4[MAXN * 2];
__device__ float g_res4[MAXN * 2];
__device__ float g_el4[MAXN];
__device__ float g_er4[MAXN];

// ---------------------------------------------------------------------------
// CSR build
// ---------------------------------------------------------------------------
__global__ void zero_kernel(int n) {
    int i = blockIdx.x * blockDim.x + threadIdx.x;
    if (i < n) { g_deg[i] = 0; g_cur[i] = 0; }
}

__global__ void hist_kernel(const int* __restrict__ dst, int e) {
    int i = blockIdx.x * blockDim.x + threadIdx.x;
    if (i < e) atomicAdd(&g_deg[dst[i]], 1);
}

__global__ void scan1_kernel(int n) {
    __shared__ int sm[1024];
    int t = threadIdx.x;
    int i = blockIdx.x * 1024 + t;
    int v = (i < n) ? g_deg[i] : 0;
    sm[t] = v;
    __syncthreads();
    for (int o = 1; o < 1024; o <<= 1) {
        int u = (t >= o) ? sm[t - o] : 0;
        __syncthreads();
        sm[t] += u;
        __syncthreads();
    }
    if (i < n) g_off[i] = sm[t] - v;
    if (t == 1023) g_bsum[blockIdx.x] = sm[1023];
}

__global__ void scan2_kernel(int nb, int n) {
    __shared__ int sm[128];
    int t = threadIdx.x;
    int v = (t < nb) ? g_bsum[t] : 0;
    sm[t] = v;
    __syncthreads();
    for (int o = 1; o < 128; o <<= 1) {
        int u = (t >= o) ? sm[t - o] : 0;
        __syncthreads();
        sm[t] += u;
        __syncthreads();
    }
    if (t < nb) g_boff[t] = sm[t] - v;
    if (t == 127) g_off[n] = sm[127];
}

__global__ void scan3_kernel(int n) {
    int i = blockIdx.x * blockDim.x + threadIdx.x;
    if (i < n) g_off[i] += g_boff[i >> 10];
}

__global__ void scatter_kernel(const int* __restrict__ src,
                               const int* __restrict__ dst, int e) {
    int i = blockIdx.x * blockDim.x + threadIdx.x;
    if (i < e) {
        int d = dst[i];
        int pos = atomicAdd(&g_cur[d], 1);
        g_csrc[g_off[d] + pos] = src[i];
    }
}

// ---------------------------------------------------------------------------
// Touch kernel (prewarm only)
// ---------------------------------------------------------------------------
__global__ void touch_kernel() {
    long i = (long)blockIdx.x * blockDim.x + threadIdx.x;
    long tot = (long)MAXN * 128;
    if (i < (long)MAXN * 16) g_hh[i] = make_uint4(0, 0, 0, 0);
    if (i < tot) g_act[i] = 0.f;
    if (i < MAXE) g_csrc[i] = 0;
    if (i < MAXN) {
        g_el[i * 4] = 0.f; g_er[i * 4] = 0.f;
        g_el4[i] = 0.f; g_er4[i] = 0.f;
        g_h4[i * 2] = 0.f; g_res4[i * 2] = 0.f;
        g_deg[i] = 0; g_cur[i] = 0; g_off[i] = 0;
    }
    if (i < 128) { g_bsum[i] = 0; g_boff[i] = 0; }
}

// ---------------------------------------------------------------------------
// Tensor-core GEMM: g_hh[n,128](fp16) = X[n,128] @ W[128,128] + el/er.
// ---------------------------------------------------------------------------
#define ASTRIDE 136
#define SMEM_TC (2 * 128 * ASTRIDE * 2)

__global__ __launch_bounds__(256) void gemm_tc_kernel(
    const float* __restrict__ X_ext, const float* __restrict__ W,
    const float* __restrict__ al, const float* __restrict__ ar,
    int n, int use_act) {
    const float* X = use_act ? (const float*)g_act : X_ext;
    extern __shared__ __half sm[];
    __half* As = sm;
    __half* Bs = sm + 128 * ASTRIDE;

    int tid = threadIdx.x;
    int lane = tid & 31;
    int wid = tid >> 5;
    int row0 = blockIdx.x * 128;

    for (int i = tid; i < 128 * 32; i += 256) {
        int r = i >> 5;
        int kq = i & 31;
        int row = row0 + r;
        float4 v = make_float4(0.f, 0.f, 0.f, 0.f);
        if (row < n) v = ((const float4*)X)[row * 32 + kq];
        __half2 p0 = __floats2half2_rn(v.x, v.y);
        __half2 p1 = __floats2half2_rn(v.z, v.w);
        uint2 pk;
        pk.x = *reinterpret_cast<unsigned*>(&p0);
        pk.y = *reinterpret_cast<unsigned*>(&p1);
        *reinterpret_cast<uint2*>(&As[r * ASTRIDE + kq * 4]) = pk;
    }
    for (int i = tid; i < 128 * 32; i += 256) {
        int r = i >> 5;
        int kq = i & 31;
        float4 v = ((const float4*)W)[r * 32 + kq];
        __half2 p0 = __floats2half2_rn(v.x, v.y);
        __half2 p1 = __floats2half2_rn(v.z, v.w);
        uint2 pk;
        pk.x = *reinterpret_cast<unsigned*>(&p0);
        pk.y = *reinterpret_cast<unsigned*>(&p1);
        *reinterpret_cast<uint2*>(&Bs[r * ASTRIDE + kq * 4]) = pk;
    }
    __syncthreads();

    int mrow = wid * 16;
    int row_sel = lane & 15;
    int col_off8 = (lane >> 4) << 3;
    float c[16][4];
#pragma unroll
    for (int a = 0; a < 16; a++)
#pragma unroll
        for (int j = 0; j < 4; j++) c[a][j] = 0.f;

#pragma unroll
    for (int ks = 0; ks < 8; ks++) {
        unsigned a0, a1, a2, a3;
        {
            unsigned addr = (unsigned)__cvta_generic_to_shared(
                &As[(mrow + row_sel) * ASTRIDE + ks * 16 + col_off8]);
            asm volatile(
                "ldmatrix.sync.aligned.m8n8.x4.shared.b16 {%0,%1,%2,%3}, [%4];"
                : "=r"(a0), "=r"(a1), "=r"(a2), "=r"(a3) : "r"(addr));
        }
#pragma unroll
        for (int nb2 = 0; nb2 < 8; nb2++) {
            unsigned b0, b1, b2, b3;
            unsigned addr = (unsigned)__cvta_generic_to_shared(
                &Bs[(ks * 16 + row_sel) * ASTRIDE + nb2 * 16 + col_off8]);
            asm volatile(
                "ldmatrix.sync.aligned.m8n8.x4.trans.shared.b16 {%0,%1,%2,%3}, [%4];"
                : "=r"(b0), "=r"(b1), "=r"(b2), "=r"(b3) : "r"(addr));
            int na = nb2 * 2;
            asm volatile(
                "mma.sync.aligned.m16n8k16.row.col.f32.f16.f16.f32 "
                "{%0,%1,%2,%3}, {%4,%5,%6,%7}, {%8,%9}, {%0,%1,%2,%3};"
                : "+f"(c[na][0]), "+f"(c[na][1]), "+f"(c[na][2]), "+f"(c[na][3])
                : "r"(a0), "r"(a1), "r"(a2), "r"(a3), "r"(b0), "r"(b1));
            asm volatile(
                "mma.sync.aligned.m16n8k16.row.col.f32.f16.f16.f32 "
                "{%0,%1,%2,%3}, {%4,%5,%6,%7}, {%8,%9}, {%0,%1,%2,%3};"
                : "+f"(c[na + 1][0]), "+f"(c[na + 1][1]), "+f"(c[na + 1][2]), "+f"(c[na + 1][3])
                : "r"(a0), "r"(a1), "r"(a2), "r"(a3), "r"(b2), "r"(b3));
        }
    }
    __syncthreads();

    {
        int r0 = mrow + (lane >> 2);
        int cc = (lane & 3) * 2;
#pragma unroll
        for (int na = 0; na < 16; na++) {
            __half2 lo = __floats2half2_rn(c[na][0], c[na][1]);
            __half2 hi = __floats2half2_rn(c[na][2], c[na][3]);
            *reinterpret_cast<unsigned*>(&As[r0 * ASTRIDE + na * 8 + cc]) =
                *reinterpret_cast<unsigned*>(&lo);
            *reinterpret_cast<unsigned*>(&As[(r0 + 8) * ASTRIDE + na * 8 + cc]) =
                *reinterpret_cast<unsigned*>(&hi);
        }
    }
    __syncthreads();

    {
        int r = tid >> 1;
        int hsel = tid & 1;
        int row = row0 + r;
        if (row < n) {
            uint4 cv[8];
#pragma unroll
            for (int j = 0; j < 8; j++)
                cv[j] = *reinterpret_cast<uint4*>(&As[r * ASTRIDE + hsel * 64 + j * 8]);
#pragma unroll
            for (int j = 0; j < 8; j++)
                g_hh[row * 16 + hsel * 8 + j] = cv[j];
            int h0 = hsel * 2;
            float el0 = 0.f, er0 = 0.f, el1 = 0.f, er1 = 0.f;
#pragma unroll
            for (int j = 0; j < 8; j++) {
                const __half2* hp = reinterpret_cast<const __half2*>(&cv[j]);
#pragma unroll
                for (int q = 0; q < 4; q++) {
                    float2 f = __half22float2(hp[q]);
                    int d = (j * 8 + q * 2) & 31;
                    if (j < 4) {
                        el0 += f.x * al[h0 * 32 + d]     + f.y * al[h0 * 32 + d + 1];
                        er0 += f.x * ar[h0 * 32 + d]     + f.y * ar[h0 * 32 + d + 1];
                    } else {
                        el1 += f.x * al[(h0 + 1) * 32 + d] + f.y * al[(h0 + 1) * 32 + d + 1];
                        er1 += f.x * ar[(h0 + 1) * 32 + d] + f.y * ar[(h0 + 1) * 32 + d + 1];
                    }
                }
            }
            *reinterpret_cast<float2*>(&g_el[row * 4 + h0]) = make_float2(el0, el1);
            *reinterpret_cast<float2*>(&g_er[row * 4 + h0]) = make_float2(er0, er1);
        }
    }
}

// ---------------------------------------------------------------------------
// Single-pass softmax-aggregate + residual + bias + ELU.  Warp per dst node
// (R12 form).  fuse4: agg3 also computes the layer-4 projections from the
// freshly produced activation row (lane holds features 4*lane..4*lane+3).
// ---------------------------------------------------------------------------
__device__ __forceinline__ float lrelu(float x) { return x > 0.f ? x : 0.2f * x; }

__global__ __launch_bounds__(256) void agg_kernel(
    const float* prev_ext, const float* __restrict__ bias, int n, int use_act,
    int fuse4, const float* __restrict__ W4, const float* __restrict__ Wres4,
    const float* __restrict__ al4, const float* __restrict__ ar4) {
    int w = (blockIdx.x * blockDim.x + threadIdx.x) >> 5;
    if (w >= n) return;
    const float* prev = use_act ? (const float*)g_act : prev_ext;
    int lane = threadIdx.x & 31;
    int head = lane >> 3;
    int e0 = g_off[w];
    int e1 = g_off[w + 1];

    float erh = __ldg(&g_er[w * 4 + head]);

    const uint2* hp = (const uint2*)g_hh;
    float s = 0.f;
    float4 acc = make_float4(0.f, 0.f, 0.f, 0.f);
#pragma unroll 4
    for (int i = e0; i < e1; ++i) {
        int sn = __ldg(&g_csrc[i]);
        float e = lrelu(__ldg(&g_el[sn * 4 + head]) + erh);
        float p = __expf(e);
        s += p;
        uint2 raw = __ldg(&hp[sn * 32 + lane]);
        __half2 ha = *reinterpret_cast<const __half2*>(&raw.x);
        __half2 hb = *reinterpret_cast<const __half2*>(&raw.y);
        float2 f01 = __half22float2(ha);
        float2 f23 = __half22float2(hb);
        acc.x += p * f01.x;
        acc.y += p * f01.y;
        acc.z += p * f23.x;
        acc.w += p * f23.y;
    }
    float inv = s > 0.f ? 1.f / s : 0.f;

    float4 r = ((const float4*)prev)[w * 32 + lane];
    float4 bb = ((const float4*)bias)[lane];
    float o0 = acc.x * inv + r.x + bb.x;
    float o1 = acc.y * inv + r.y + bb.y;
    float o2 = acc.z * inv + r.z + bb.z;
    float o3 = acc.w * inv + r.w + bb.w;
    o0 = o0 > 0.f ? o0 : expm1f(o0);
    o1 = o1 > 0.f ? o1 : expm1f(o1);
    o2 = o2 > 0.f ? o2 : expm1f(o2);
    o3 = o3 > 0.f ? o3 : expm1f(o3);
    ((float4*)g_act)[w * 32 + lane] = make_float4(o0, o1, o2, o3);

    if (fuse4) {
        // gemv4 fused: lane's o0..o3 are act features 4*lane..4*lane+3.
        float4 w0 = ((const float4*)W4)[lane * 2];
        float4 w1 = ((const float4*)W4)[lane * 2 + 1];
        float4 q0v = ((const float4*)Wres4)[lane * 2];
        float4 q1v = ((const float4*)Wres4)[lane * 2 + 1];
        float h40 = o0 * w0.x + o1 * w0.z + o2 * w1.x + o3 * w1.z;
        float h41 = o0 * w0.y + o1 * w0.w + o2 * w1.y + o3 * w1.w;
        float q40 = o0 * q0v.x + o1 * q0v.z + o2 * q1v.x + o3 * q1v.z;
        float q41 = o0 * q0v.y + o1 * q0v.w + o2 * q1v.y + o3 * q1v.w;
#pragma unroll
        for (int o = 16; o; o >>= 1) {
            h40 += __shfl_xor_sync(0xffffffffu, h40, o);
            h41 += __shfl_xor_sync(0xffffffffu, h41, o);
            q40 += __shfl_xor_sync(0xffffffffu, q40, o);
            q41 += __shfl_xor_sync(0xffffffffu, q41, o);
        }
        if (lane == 0) {
            g_h4[w * 2] = h40;
            g_h4[w * 2 + 1] = h41;
            g_res4[w * 2] = q40;
            g_res4[w * 2 + 1] = q41;
            g_el4[w] = h40 * al4[0] + h41 * al4[1];
            g_er4[w] = h40 * ar4[0] + h41 * ar4[1];
        }
    }
}

// Single-pass layer-4 aggregation: lanes stride edges, one warp reduction.
__global__ __launch_bounds__(256) void agg4_kernel(
    const float* __restrict__ b4, float* __restrict__ out, int n) {
    int w = (blockIdx.x * blockDim.x + threadIdx.x) >> 5;
    if (w >= n) return;
    int lane = threadIdx.x & 31;
    int e0 = g_off[w];
    int e1 = g_off[w + 1];
    float erv = g_er4[w];

    float s = 0.f, a0 = 0.f, a1 = 0.f;
    for (int i = e0 + lane; i < e1; i += 32) {
        int sn = g_csrc[i];
        float e = lrelu(g_el4[sn] + erv);
        float p = __expf(e);
        s += p;
        float2 hv = ((const float2*)g_h4)[sn];
        a0 += p * hv.x;
        a1 += p * hv.y;
    }
#pragma unroll
    for (int o = 16; o; o >>= 1) {
        s  += __shfl_xor_sync(0xffffffffu, s, o);
        a0 += __shfl_xor_sync(0xffffffffu, a0, o);
        a1 += __shfl_xor_sync(0xffffffffu, a1, o);
    }
    float inv = s > 0.f ? 1.f / s : 0.f;
    if (lane == 0) {
        out[w * 2]     = a0 * inv + g_res4[w * 2]     + b4[0];
        out[w * 2 + 1] = a1 * inv + g_res4[w * 2 + 1] + b4[1];
    }
}

// ---------------------------------------------------------------------------
// Constructor: EAGER loading, context, smem attribute, prewarm, aux stream.
// ---------------------------------------------------------------------------
namespace {
cudaStream_t g_saux;
cudaEvent_t  g_ev_fork;
cudaEvent_t  g_ev_join;

struct Prewarm {
    Prewarm() {
        setenv("CUDA_MODULE_LOADING", "EAGER", 1);
        cudaFree(0);

        cudaStreamCreateWithFlags(&g_saux, cudaStreamNonBlocking);
        cudaEventCreateWithFlags(&g_ev_fork, cudaEventDisableTiming);
        cudaEventCreateWithFlags(&g_ev_join, cudaEventDisableTiming);
        cudaFuncSetAttribute(gemm_tc_kernel,
                             cudaFuncAttributeMaxDynamicSharedMemorySize, SMEM_TC);

        void* ph = nullptr;
        void* pd = nullptr;
        cudaGetSymbolAddress(&ph, g_act);
        cudaGetSymbolAddress(&pd, g_deg);
        const float* fp = (const float*)ph;
        const int*   ip = (const int*)pd;
        float*       op = (float*)ph;

        int nbn = (MAXN + 255) / 256;
        int nbe = (MAXE + 255) / 256;
        int nbw = (MAXN + 7) / 8;
        int nbg = (MAXN + 127) / 128;
        int nbs = (MAXN + 1023) / 1024;
        long tot = (long)MAXN * 128;
        int nbt = (int)((tot + 255) / 256);

        touch_kernel<<<nbt, 256>>>();
        zero_kernel<<<nbn, 256>>>(0);
        hist_kernel<<<nbe, 256>>>(ip, 0);
        scan1_kernel<<<nbs, 1024>>>(0);
        scan2_kernel<<<1, 128>>>(0, 0);
        scan3_kernel<<<nbn, 256>>>(0);
        scatter_kernel<<<nbe, 256>>>(ip, ip, 0);
        gemm_tc_kernel<<<nbg, 256, SMEM_TC>>>(fp, fp, fp, fp, 0, 1);
        agg_kernel<<<nbw, 256>>>(fp, fp, 0, 1, 1, fp, fp, fp, fp);
        agg4_kernel<<<nbw, 256>>>(fp, op, 0);
        zero_kernel<<<nbn, 256, 0, g_saux>>>(0);
        touch_kernel<<<nbt, 256>>>();
        cudaDeviceSynchronize();
    }
};
Prewarm g_prewarm;
}  // namespace

// ---------------------------------------------------------------------------
// Launch
// ---------------------------------------------------------------------------
extern "C" void kernel_launch(void* const* d_in, const int* in_sizes, int n_in,
                              void* d_out, int out_size) {
    const float* x     = (const float*)d_in[0];
    const int*   src   = (const int*)d_in[1];
    const int*   dst   = (const int*)d_in[2];
    const float* W1    = (const float*)d_in[3];
    const float* al1   = (const float*)d_in[4];
    const float* ar1   = (const float*)d_in[5];
    const float* b1    = (const float*)d_in[6];
    const float* W2    = (const float*)d_in[7];
    const float* al2   = (const float*)d_in[8];
    const float* ar2   = (const float*)d_in[9];
    const float* b2    = (const float*)d_in[10];
    const float* W3    = (const float*)d_in[11];
    const float* al3   = (const float*)d_in[12];
    const float* ar3   = (const float*)d_in[13];
    const float* b3    = (const float*)d_in[14];
    const float* W4    = (const float*)d_in[15];
    const float* al4   = (const float*)d_in[16];
    const float* ar4   = (const float*)d_in[17];
    const float* b4    = (const float*)d_in[18];
    const float* Wres4 = (const float*)d_in[19];
    float* out = (float*)d_out;

    int n = in_sizes[0] / 128;
    int e = in_sizes[1];
    int nb = (n + 1023) / 1024;

    int nbw = (n + 7) / 8;
    int nbg = (n + 127) / 128;

    // Fork: CSR build on aux stream, layer-1 GEMM on main stream.
    cudaEventRecord(g_ev_fork, 0);
    cudaStreamWaitEvent(g_saux, g_ev_fork, 0);

    zero_kernel<<<(n + 255) / 256, 256, 0, g_saux>>>(n);
    hist_kernel<<<(e + 255) / 256, 256, 0, g_saux>>>(dst, e);
    scan1_kernel<<<nb, 1024, 0, g_saux>>>(n);
    scan2_kernel<<<1, 128, 0, g_saux>>>(nb, n);
    scan3_kernel<<<(n + 255) / 256, 256, 0, g_saux>>>(n);
    scatter_kernel<<<(e + 255) / 256, 256, 0, g_saux>>>(src, dst, e);
    cudaEventRecord(g_ev_join, g_saux);

    gemm_tc_kernel<<<nbg, 256, SMEM_TC>>>(x, W1, al1, ar1, n, 0);

    cudaStreamWaitEvent(0, g_ev_join, 0);
    agg_kernel<<<nbw, 256>>>(x, b1, n, 0, 0, nullptr, nullptr, nullptr, nullptr);

    gemm_tc_kernel<<<nbg, 256, SMEM_TC>>>(nullptr, W2, al2, ar2, n, 1);
    agg_kernel<<<nbw, 256>>>(nullptr, b2, n, 1, 0, nullptr, nullptr, nullptr, nullptr);

    gemm_tc_kernel<<<nbg, 256, SMEM_TC>>>(nullptr, W3, al3, ar3, n, 1);
    agg_kernel<<<nbw, 256>>>(nullptr, b3, n, 1, 1, W4, Wres4, al4, ar4);

    agg4_kernel<<<nbw, 256>>>(b4, out, n);
}